// round 15
// baseline (speedup 1.0000x reference)
#include <cuda_runtime.h>
#include <math.h>

#define VOCAB 50257
#define EMB   128
#define VPB   96           // 96 floats = 384 B = 3 full lines, 128B-aligned chunks
#define GRID  524          // ceil(50257/96); co-resident (524 <= 148*4)

// ---------------- persistent scratch (no allocations allowed) ----------------
__device__ float    g_h[EMB];       // hidden accumulator; zero at load, re-zeroed each run
__device__ float    g_m[GRID];      // per-block logit max
__device__ float    g_z[GRID];      // per-block sum exp(l - m_b)
__device__ unsigned g_barrier = 0;  // monotone arrival counter (reset each run)
__device__ unsigned g_done    = 0;  // completion counter for reset

// ---------------- grid barrier with nanosleep backoff ------------------------
__device__ __forceinline__ void grid_bar(unsigned target) {
    __syncthreads();
    if (threadIdx.x == 0) {
        __threadfence();
        unsigned arrived = atomicAdd(&g_barrier, 1u) + 1u;
        if (arrived < target) {
            volatile unsigned* p = &g_barrier;
            while (*p < target) __nanosleep(64);
        }
        __threadfence();
    }
    __syncthreads();
}

// ---------------- block reductions (fixed order -> deterministic) -----------
__device__ __forceinline__ float blockReduceSum(float v, float* sm) {
    int lane = threadIdx.x & 31, warp = threadIdx.x >> 5;
#pragma unroll
    for (int o = 16; o; o >>= 1) v += __shfl_xor_sync(0xffffffffu, v, o);
    if (lane == 0) sm[warp] = v;
    __syncthreads();
    v = (warp == 0 && lane < 8) ? sm[lane] : 0.f;
    if (warp == 0) {
#pragma unroll
        for (int o = 4; o; o >>= 1) v += __shfl_xor_sync(0xffffffffu, v, o);
    }
    return v;  // valid on thread 0
}

__device__ __forceinline__ float blockReduceMax(float v, float* sm) {
    int lane = threadIdx.x & 31, warp = threadIdx.x >> 5;
#pragma unroll
    for (int o = 16; o; o >>= 1) v = fmaxf(v, __shfl_xor_sync(0xffffffffu, v, o));
    if (lane == 0) sm[warp] = v;
    __syncthreads();
    v = (warp == 0 && lane < 8) ? sm[lane] : -3.402823466e38f;
    if (warp == 0) {
#pragma unroll
        for (int o = 4; o; o >>= 1) v = fmaxf(v, __shfl_xor_sync(0xffffffffu, v, o));
    }
    return v;  // valid on thread 0
}

// ---------------- the single persistent kernel ------------------------------
__global__ void __launch_bounds__(256, 4)
w2v_persist(const float* __restrict__ oh, const float* __restrict__ Wq,
            const float* __restrict__ bq, const float* __restrict__ Ww,
            const float* __restrict__ bw, float* __restrict__ out,
            int rows, float inv_len)
{
    __shared__ float sh_sp[8][VPB];   // per-warp column-sum partials
    __shared__ float sh_s[VPB];       // folded column sums for this chunk
    __shared__ alignas(16) float sh_hid[EMB];
    __shared__ float sh_log[VPB];
    __shared__ float sh_red[8];
    __shared__ float sh_bc;

    const int tid  = threadIdx.x;
    const int lane = tid & 31, warp = tid >> 5;
    const int b    = blockIdx.x;
    const int v0   = b * VPB;
    const int cnt  = min(VPB, VOCAB - v0);     // 49..96, >0 for all blocks

    // ===== Phase A1: column sums; all 8 warps, 8 rows in flight per warp =====
    {
        float a0 = 0.f, a1 = 0.f, a2 = 0.f;
        const size_t S = (size_t)VOCAB;
        const float* base = oh + v0;
        if (cnt == VPB) {
            int t = warp;
            for (; t + 56 < rows; t += 64) {          // 8 rows in flight
                const float* p0 = base + (size_t)(t     ) * S;
                const float* p1 = base + (size_t)(t +  8) * S;
                const float* p2 = base + (size_t)(t + 16) * S;
                const float* p3 = base + (size_t)(t + 24) * S;
                const float* p4 = base + (size_t)(t + 32) * S;
                const float* p5 = base + (size_t)(t + 40) * S;
                const float* p6 = base + (size_t)(t + 48) * S;
                const float* p7 = base + (size_t)(t + 56) * S;
                float x00 = p0[lane], x01 = p0[lane+32], x02 = p0[lane+64];
                float x10 = p1[lane], x11 = p1[lane+32], x12 = p1[lane+64];
                float x20 = p2[lane], x21 = p2[lane+32], x22 = p2[lane+64];
                float x30 = p3[lane], x31 = p3[lane+32], x32 = p3[lane+64];
                float x40 = p4[lane], x41 = p4[lane+32], x42 = p4[lane+64];
                float x50 = p5[lane], x51 = p5[lane+32], x52 = p5[lane+64];
                float x60 = p6[lane], x61 = p6[lane+32], x62 = p6[lane+64];
                float x70 = p7[lane], x71 = p7[lane+32], x72 = p7[lane+64];
                a0 += ((x00 + x10) + (x20 + x30)) + ((x40 + x50) + (x60 + x70));
                a1 += ((x01 + x11) + (x21 + x31)) + ((x41 + x51) + (x61 + x71));
                a2 += ((x02 + x12) + (x22 + x32)) + ((x42 + x52) + (x62 + x72));
            }
            for (; t < rows; t += 8) {
                const float* p = base + (size_t)t * S;
                a0 += p[lane]; a1 += p[lane+32]; a2 += p[lane+64];
            }
        } else {
            const bool ok0 = lane < cnt, ok1 = (lane+32) < cnt, ok2 = (lane+64) < cnt;
            for (int t = warp; t < rows; t += 8) {
                const float* p = base + (size_t)t * S;
                if (ok0) a0 += p[lane];
                if (ok1) a1 += p[lane+32];
                if (ok2) a2 += p[lane+64];
            }
        }
        sh_sp[warp][lane]      = a0;
        sh_sp[warp][lane + 32] = a1;
        sh_sp[warp][lane + 64] = a2;
        __syncthreads();
        if (tid < VPB) {
            float s = 0.f;
#pragma unroll
            for (int w = 0; w < 8; ++w) s += sh_sp[w][tid];
            sh_s[tid] = s;
        }
        __syncthreads();
    }

    // ===== Phase A2: warp-per-e, coalesced (1-2 wavefronts per LDG) =====
    // Warp w handles e = w*16 .. w*16+15; 32 lanes read the whole 384B segment.
    {
        const int e0 = warp * 16;
        const float ss0 = sh_s[lane];
        const float ss1 = sh_s[lane + 32];
        const float ss2 = sh_s[lane + 64];
        const bool ok0 = lane < cnt, ok1 = (lane+32) < cnt, ok2 = (lane+64) < cnt;
#pragma unroll 4
        for (int i = 0; i < 16; ++i) {
            const int e = e0 + i;
            const float* wr = Wq + (size_t)e * VOCAB + v0;
            float acc;
            if (cnt == VPB) {
                acc = ss0 * wr[lane] + ss1 * wr[lane + 32] + ss2 * wr[lane + 64];
            } else {
                acc = 0.f;
                if (ok0) acc += ss0 * wr[lane];
                if (ok1) acc += ss1 * wr[lane + 32];
                if (ok2) acc += ss2 * wr[lane + 64];
            }
#pragma unroll
            for (int o = 16; o; o >>= 1) acc += __shfl_xor_sync(0xffffffffu, acc, o);
            if (lane == 0) atomicAdd(&g_h[e], acc);
        }
    }

    // ===== Pre-barrier: issue phase B's j=0 Ww loads into registers =====
    // Independent register-destined LDGs; their latency + DRAM traffic
    // overlap the barrier-wait dead window (no STS in the chain, cf. R12).
    const int gB = (tid >> 3) & 3;     // 8-lane group within warp
    const int lB = tid & 7;
    const int r0_  = (warp << 2) + gB;            // j=0 row for this group
    const int rr0_ = min(r0_, cnt - 1);
    const float4* wrow0 = reinterpret_cast<const float4*>(Ww + (size_t)(v0 + rr0_) * EMB);
    const float4 pw0 = wrow0[lB];
    const float4 pw1 = wrow0[lB + 8];
    const float4 pw2 = wrow0[lB + 16];
    const float4 pw3 = wrow0[lB + 24];
    const float  pbw = __ldg(bw + v0 + rr0_);

    grid_bar(1u * GRID);

    // ===== Phase B: logits; 8 lanes/row x 4 rows/warp, 3-shfl reduce =====
    {
        if (tid < EMB)
            sh_hid[tid] = g_h[tid] * inv_len + bq[tid];
        __syncthreads();

        const float4 h0 = reinterpret_cast<const float4*>(sh_hid)[lB];
        const float4 h1 = reinterpret_cast<const float4*>(sh_hid)[lB +  8];
        const float4 h2 = reinterpret_cast<const float4*>(sh_hid)[lB + 16];
        const float4 h3 = reinterpret_cast<const float4*>(sh_hid)[lB + 24];
        float wmax = -3.402823466e38f;

        // j = 0: use preloaded registers
        {
            float p = (pw0.x*h0.x + pw0.y*h0.y + pw0.z*h0.z + pw0.w*h0.w)
                    + (pw1.x*h1.x + pw1.y*h1.y + pw1.z*h1.z + pw1.w*h1.w)
                    + (pw2.x*h2.x + pw2.y*h2.y + pw2.z*h2.z + pw2.w*h2.w)
                    + (pw3.x*h3.x + pw3.y*h3.y + pw3.z*h3.z + pw3.w*h3.w);
            p += __shfl_xor_sync(0xffffffffu, p, 1);
            p += __shfl_xor_sync(0xffffffffu, p, 2);
            p += __shfl_xor_sync(0xffffffffu, p, 4);
            const float lg = p + pbw;
            if (r0_ < cnt) {
                if (lB == 0) sh_log[r0_] = lg;
                wmax = fmaxf(wmax, lg);
            }
        }
        // j = 1, 2: demand loads (as in R8)
#pragma unroll
        for (int j = 1; j < 3; ++j) {
            const int r  = j * 32 + (warp << 2) + gB;
            const int rr = min(r, cnt - 1);
            const float4* wrow = reinterpret_cast<const float4*>(Ww + (size_t)(v0 + rr) * EMB);
            const float4 w0 = wrow[lB], w1 = wrow[lB + 8], w2 = wrow[lB + 16], w3 = wrow[lB + 24];
            float p = (w0.x*h0.x + w0.y*h0.y + w0.z*h0.z + w0.w*h0.w)
                    + (w1.x*h1.x + w1.y*h1.y + w1.z*h1.z + w1.w*h1.w)
                    + (w2.x*h2.x + w2.y*h2.y + w2.z*h2.z + w2.w*h2.w)
                    + (w3.x*h3.x + w3.y*h3.y + w3.z*h3.z + w3.w*h3.w);
            p += __shfl_xor_sync(0xffffffffu, p, 1);
            p += __shfl_xor_sync(0xffffffffu, p, 2);
            p += __shfl_xor_sync(0xffffffffu, p, 4);
            const float lg = p + __ldg(bw + v0 + rr);
            if (r < cnt) {
                if (lB == 0) sh_log[r] = lg;
                wmax = fmaxf(wmax, lg);
            }
        }
        // fold full warp max
        {
            float wm = wmax;
#pragma unroll
            for (int o = 16; o; o >>= 1) wm = fmaxf(wm, __shfl_xor_sync(0xffffffffu, wm, o));
            if (lane == 0) sh_red[warp] = wm;
        }
        __syncthreads();
        if (tid == 0) {
            float m = sh_red[0];
#pragma unroll
            for (int i = 1; i < 8; ++i) m = fmaxf(m, sh_red[i]);
            sh_bc = m;
        }
        __syncthreads();
        const float m_b = sh_bc;
        __syncthreads();  // protect sh_red reuse inside blockReduceSum
        float ez = (tid < cnt) ? expf(sh_log[tid] - m_b) : 0.f;
        const float Z = blockReduceSum(ez, sh_red);
        if (tid == 0) { g_m[b] = m_b; g_z[b] = Z; }
    }
    grid_bar(2u * GRID);

    // ===== Phase C: merge (m,Z) -> LSE; write out; restore g_h to zero =====
    {
        if (b == 0 && tid < EMB) g_h[tid] = 0.f;   // all g_h reads done pre-barrier

        float lm = -3.402823466e38f;
        for (int i = tid; i < GRID; i += 256) lm = fmaxf(lm, g_m[i]);
        float M = blockReduceMax(lm, sh_red);
        if (tid == 0) sh_bc = M;
        __syncthreads();
        M = sh_bc;
        __syncthreads();
        float lz = 0.f;
        for (int i = tid; i < GRID; i += 256) lz += g_z[i] * expf(g_m[i] - M);
        const float Z = blockReduceSum(lz, sh_red);
        if (tid == 0) sh_bc = M + logf(Z);
        __syncthreads();
        const float lse = sh_bc;
        if (tid < cnt) out[v0 + tid] = sh_log[tid] - lse;
    }

    // ===== Reset barrier state for next graph replay =====
    __threadfence();
    __syncthreads();
    if (tid == 0) {
        const unsigned old = atomicAdd(&g_done, 1u);
        if (old == GRID - 1u) {        // last block of the whole grid
            g_barrier = 0u;            // nobody spins anymore: all passed barrier 2
            g_done    = 0u;
            __threadfence();
        }
    }
}

// ---------------- launch -----------------------------------------------------
extern "C" void kernel_launch(void* const* d_in, const int* in_sizes, int n_in,
                              void* d_out, int out_size) {
    const float* oh = (const float*)d_in[0];
    // d_in[1] is the scalar `length` (== CTX); rows derived from shape
    const float* Wq = (const float*)d_in[2];
    const float* bq = (const float*)d_in[3];
    const float* Ww = (const float*)d_in[4];
    const float* bw = (const float*)d_in[5];
    float* out = (float*)d_out;

    const int rows = in_sizes[0] / VOCAB;       // 200
    const float inv_len = 1.0f / (float)rows;   // length == CTX here

    w2v_persist<<<GRID, 256>>>(oh, Wq, bq, Ww, bw, out, rows, inv_len);
}

// round 17
// speedup vs baseline: 1.6895x; 1.6895x over previous
#include <cuda_runtime.h>
#include <math.h>

#define VOCAB 50257
#define EMB   128
#define VPB   128          // 128 floats = 512 B = 4 full lines, 128B-aligned chunks
#define GRID  393          // ceil(50257/128); co-resident (393 <= 148*3)

// ---------------- persistent scratch (no allocations allowed) ----------------
__device__ float    g_h[EMB];       // hidden accumulator; zero at load, re-zeroed each run
__device__ float    g_m[GRID];      // per-block logit max
__device__ float    g_z[GRID];      // per-block sum exp(l - m_b)
__device__ unsigned g_barrier = 0;  // monotone arrival counter (reset each run)
__device__ unsigned g_done    = 0;  // completion counter for reset

// ---------------- grid barrier with nanosleep backoff ------------------------
__device__ __forceinline__ void grid_bar(unsigned target) {
    __syncthreads();
    if (threadIdx.x == 0) {
        __threadfence();
        unsigned arrived = atomicAdd(&g_barrier, 1u) + 1u;
        if (arrived < target) {
            volatile unsigned* p = &g_barrier;
            while (*p < target) __nanosleep(64);
        }
        __threadfence();
    }
    __syncthreads();
}

// ---------------- block reductions (fixed order -> deterministic) -----------
__device__ __forceinline__ float blockReduceSum(float v, float* sm) {
    int lane = threadIdx.x & 31, warp = threadIdx.x >> 5;
#pragma unroll
    for (int o = 16; o; o >>= 1) v += __shfl_xor_sync(0xffffffffu, v, o);
    if (lane == 0) sm[warp] = v;
    __syncthreads();
    v = (warp == 0 && lane < 8) ? sm[lane] : 0.f;
    if (warp == 0) {
#pragma unroll
        for (int o = 4; o; o >>= 1) v += __shfl_xor_sync(0xffffffffu, v, o);
    }
    return v;  // valid on thread 0
}

__device__ __forceinline__ float blockReduceMax(float v, float* sm) {
    int lane = threadIdx.x & 31, warp = threadIdx.x >> 5;
#pragma unroll
    for (int o = 16; o; o >>= 1) v = fmaxf(v, __shfl_xor_sync(0xffffffffu, v, o));
    if (lane == 0) sm[warp] = v;
    __syncthreads();
    v = (warp == 0 && lane < 8) ? sm[lane] : -3.402823466e38f;
    if (warp == 0) {
#pragma unroll
        for (int o = 4; o; o >>= 1) v = fmaxf(v, __shfl_xor_sync(0xffffffffu, v, o));
    }
    return v;  // valid on thread 0
}

// ---------------- the single persistent kernel ------------------------------
__global__ void __launch_bounds__(256, 3)
w2v_persist(const float* __restrict__ oh, const float* __restrict__ Wq,
            const float* __restrict__ bq, const float* __restrict__ Ww,
            const float* __restrict__ bw, float* __restrict__ out,
            int rows, float inv_len)
{
    __shared__ float sh_sp[8][VPB];   // per-warp column-sum partials
    __shared__ float sh_s[VPB];       // folded column sums for this chunk
    __shared__ alignas(16) float sh_hid[EMB];
    __shared__ float sh_log[VPB];
    __shared__ float sh_red[8];
    __shared__ float sh_bc;

    const int tid  = threadIdx.x;
    const int lane = tid & 31, warp = tid >> 5;
    const int b    = blockIdx.x;
    const int v0   = b * VPB;
    const int cnt  = min(VPB, VOCAB - v0);     // 81..128, >0 for all blocks

    // ===== Phase A1: column sums; 4 col-groups x 8 rows in flight per warp ===
    {
        float a0 = 0.f, a1 = 0.f, a2 = 0.f, a3 = 0.f;
        const size_t S = (size_t)VOCAB;
        const float* base = oh + v0;
        if (cnt == VPB) {
            int t = warp;
            for (; t + 56 < rows; t += 64) {          // 8 rows in flight
                const float* p0 = base + (size_t)(t     ) * S;
                const float* p1 = base + (size_t)(t +  8) * S;
                const float* p2 = base + (size_t)(t + 16) * S;
                const float* p3 = base + (size_t)(t + 24) * S;
                const float* p4 = base + (size_t)(t + 32) * S;
                const float* p5 = base + (size_t)(t + 40) * S;
                const float* p6 = base + (size_t)(t + 48) * S;
                const float* p7 = base + (size_t)(t + 56) * S;
                float x00 = p0[lane], x01 = p0[lane+32], x02 = p0[lane+64], x03 = p0[lane+96];
                float x10 = p1[lane], x11 = p1[lane+32], x12 = p1[lane+64], x13 = p1[lane+96];
                float x20 = p2[lane], x21 = p2[lane+32], x22 = p2[lane+64], x23 = p2[lane+96];
                float x30 = p3[lane], x31 = p3[lane+32], x32 = p3[lane+64], x33 = p3[lane+96];
                float x40 = p4[lane], x41 = p4[lane+32], x42 = p4[lane+64], x43 = p4[lane+96];
                float x50 = p5[lane], x51 = p5[lane+32], x52 = p5[lane+64], x53 = p5[lane+96];
                float x60 = p6[lane], x61 = p6[lane+32], x62 = p6[lane+64], x63 = p6[lane+96];
                float x70 = p7[lane], x71 = p7[lane+32], x72 = p7[lane+64], x73 = p7[lane+96];
                a0 += ((x00 + x10) + (x20 + x30)) + ((x40 + x50) + (x60 + x70));
                a1 += ((x01 + x11) + (x21 + x31)) + ((x41 + x51) + (x61 + x71));
                a2 += ((x02 + x12) + (x22 + x32)) + ((x42 + x52) + (x62 + x72));
                a3 += ((x03 + x13) + (x23 + x33)) + ((x43 + x53) + (x63 + x73));
            }
            for (; t < rows; t += 8) {
                const float* p = base + (size_t)t * S;
                a0 += p[lane]; a1 += p[lane+32]; a2 += p[lane+64]; a3 += p[lane+96];
            }
        } else {
            const bool ok0 = lane < cnt, ok1 = (lane+32) < cnt,
                       ok2 = (lane+64) < cnt, ok3 = (lane+96) < cnt;
            for (int t = warp; t < rows; t += 8) {
                const float* p = base + (size_t)t * S;
                if (ok0) a0 += p[lane];
                if (ok1) a1 += p[lane+32];
                if (ok2) a2 += p[lane+64];
                if (ok3) a3 += p[lane+96];
            }
        }
        sh_sp[warp][lane]      = a0;
        sh_sp[warp][lane + 32] = a1;
        sh_sp[warp][lane + 64] = a2;
        sh_sp[warp][lane + 96] = a3;
        __syncthreads();
        if (tid < VPB) {
            float s = 0.f;
#pragma unroll
            for (int w = 0; w < 8; ++w) s += sh_sp[w][tid];
            sh_s[tid] = s;
        }
        __syncthreads();
    }

    // ===== Phase A2: thread-per-half-row scalar dot (R14 proven form) =====
    {
        const int e    = tid >> 1;
        const int half = tid & 1;
        const int c0   = half * 64;
        const float* wr = Wq + (size_t)e * VOCAB + v0 + c0;
        float acc = 0.f;
        if (cnt == VPB) {
#pragma unroll
            for (int c = 0; c < 64; ++c) acc += sh_s[c0 + c] * wr[c];
        } else {
            const int hi = min(cnt - c0, 64);
            for (int c = 0; c < hi; ++c) acc += sh_s[c0 + c] * wr[c];
        }
        acc += __shfl_xor_sync(0xffffffffu, acc, 1);   // pair-fold halves
        if (half == 0) atomicAdd(&g_h[e], acc);
    }

    // ===== Pre-barrier: issue phase B's j=0 AND j=1 Ww loads into registers ==
    // Independent register-destined LDGs overlapping the barrier dead window.
    const int gB = (tid >> 3) & 3;     // 8-lane group within warp
    const int lB = tid & 7;
    const int r0_  = (warp << 2) + gB;            // j=0 row
    const int r1_  = 32 + r0_;                    // j=1 row
    const int rr0_ = min(r0_, cnt - 1);
    const int rr1_ = min(r1_, cnt - 1);
    const float4* wrow0 = reinterpret_cast<const float4*>(Ww + (size_t)(v0 + rr0_) * EMB);
    const float4* wrow1 = reinterpret_cast<const float4*>(Ww + (size_t)(v0 + rr1_) * EMB);
    const float4 pa0 = wrow0[lB];
    const float4 pa1 = wrow0[lB + 8];
    const float4 pa2 = wrow0[lB + 16];
    const float4 pa3 = wrow0[lB + 24];
    const float4 pb0 = wrow1[lB];
    const float4 pb1 = wrow1[lB + 8];
    const float4 pb2 = wrow1[lB + 16];
    const float4 pb3 = wrow1[lB + 24];
    const float  pbw0 = __ldg(bw + v0 + rr0_);
    const float  pbw1 = __ldg(bw + v0 + rr1_);

    grid_bar(1u * GRID);

    // ===== Phase B: logits; 8 lanes/row x 4 rows/warp, 3-shfl reduce =====
    {
        if (tid < EMB)
            sh_hid[tid] = g_h[tid] * inv_len + bq[tid];
        __syncthreads();

        const float4 h0 = reinterpret_cast<const float4*>(sh_hid)[lB];
        const float4 h1 = reinterpret_cast<const float4*>(sh_hid)[lB +  8];
        const float4 h2 = reinterpret_cast<const float4*>(sh_hid)[lB + 16];
        const float4 h3 = reinterpret_cast<const float4*>(sh_hid)[lB + 24];
        float wmax = -3.402823466e38f;

        // j = 0: preloaded registers
        {
            float p = (pa0.x*h0.x + pa0.y*h0.y + pa0.z*h0.z + pa0.w*h0.w)
                    + (pa1.x*h1.x + pa1.y*h1.y + pa1.z*h1.z + pa1.w*h1.w)
                    + (pa2.x*h2.x + pa2.y*h2.y + pa2.z*h2.z + pa2.w*h2.w)
                    + (pa3.x*h3.x + pa3.y*h3.y + pa3.z*h3.z + pa3.w*h3.w);
            p += __shfl_xor_sync(0xffffffffu, p, 1);
            p += __shfl_xor_sync(0xffffffffu, p, 2);
            p += __shfl_xor_sync(0xffffffffu, p, 4);
            const float lg = p + pbw0;
            if (r0_ < cnt) {
                if (lB == 0) sh_log[r0_] = lg;
                wmax = fmaxf(wmax, lg);
            }
        }
        // j = 1: preloaded registers
        {
            float p = (pb0.x*h0.x + pb0.y*h0.y + pb0.z*h0.z + pb0.w*h0.w)
                    + (pb1.x*h1.x + pb1.y*h1.y + pb1.z*h1.z + pb1.w*h1.w)
                    + (pb2.x*h2.x + pb2.y*h2.y + pb2.z*h2.z + pb2.w*h2.w)
                    + (pb3.x*h3.x + pb3.y*h3.y + pb3.z*h3.z + pb3.w*h3.w);
            p += __shfl_xor_sync(0xffffffffu, p, 1);
            p += __shfl_xor_sync(0xffffffffu, p, 2);
            p += __shfl_xor_sync(0xffffffffu, p, 4);
            const float lg = p + pbw1;
            if (r1_ < cnt) {
                if (lB == 0) sh_log[r1_] = lg;
                wmax = fmaxf(wmax, lg);
            }
        }
        // j = 2, 3: demand loads
#pragma unroll
        for (int j = 2; j < 4; ++j) {
            const int r  = j * 32 + (warp << 2) + gB;
            const int rr = min(r, cnt - 1);
            const float4* wrow = reinterpret_cast<const float4*>(Ww + (size_t)(v0 + rr) * EMB);
            const float4 w0 = wrow[lB], w1 = wrow[lB + 8], w2 = wrow[lB + 16], w3 = wrow[lB + 24];
            float p = (w0.x*h0.x + w0.y*h0.y + w0.z*h0.z + w0.w*h0.w)
                    + (w1.x*h1.x + w1.y*h1.y + w1.z*h1.z + w1.w*h1.w)
                    + (w2.x*h2.x + w2.y*h2.y + w2.z*h2.z + w2.w*h2.w)
                    + (w3.x*h3.x + w3.y*h3.y + w3.z*h3.z + w3.w*h3.w);
            p += __shfl_xor_sync(0xffffffffu, p, 1);
            p += __shfl_xor_sync(0xffffffffu, p, 2);
            p += __shfl_xor_sync(0xffffffffu, p, 4);
            const float lg = p + __ldg(bw + v0 + rr);
            if (r < cnt) {
                if (lB == 0) sh_log[r] = lg;
                wmax = fmaxf(wmax, lg);
            }
        }
        // fold full warp max
        {
            float wm = wmax;
#pragma unroll
            for (int o = 16; o; o >>= 1) wm = fmaxf(wm, __shfl_xor_sync(0xffffffffu, wm, o));
            if (lane == 0) sh_red[warp] = wm;
        }
        __syncthreads();
        if (tid == 0) {
            float m = sh_red[0];
#pragma unroll
            for (int i = 1; i < 8; ++i) m = fmaxf(m, sh_red[i]);
            sh_bc = m;
        }
        __syncthreads();
        const float m_b = sh_bc;
        __syncthreads();  // protect sh_red reuse inside blockReduceSum
        float ez = (tid < cnt) ? expf(sh_log[tid] - m_b) : 0.f;
        const float Z = blockReduceSum(ez, sh_red);
        if (tid == 0) { g_m[b] = m_b; g_z[b] = Z; }
    }
    grid_bar(2u * GRID);

    // ===== Phase C: merge (m,Z) -> LSE; write out; restore g_h to zero =====
    {
        if (b == 0 && tid < EMB) g_h[tid] = 0.f;   // all g_h reads done pre-barrier

        float lm = -3.402823466e38f;
        for (int i = tid; i < GRID; i += 256) lm = fmaxf(lm, g_m[i]);
        float M = blockReduceMax(lm, sh_red);
        if (tid == 0) sh_bc = M;
        __syncthreads();
        M = sh_bc;
        __syncthreads();
        float lz = 0.f;
        for (int i = tid; i < GRID; i += 256) lz += g_z[i] * expf(g_m[i] - M);
        const float Z = blockReduceSum(lz, sh_red);
        if (tid == 0) sh_bc = M + logf(Z);
        __syncthreads();
        const float lse = sh_bc;
        if (tid < cnt) out[v0 + tid] = sh_log[tid] - lse;
    }

    // ===== Reset barrier state for next graph replay =====
    __threadfence();
    __syncthreads();
    if (tid == 0) {
        const unsigned old = atomicAdd(&g_done, 1u);
        if (old == GRID - 1u) {        // last block of the whole grid
            g_barrier = 0u;            // nobody spins anymore: all passed barrier 2
            g_done    = 0u;
            __threadfence();
        }
    }
}

// ---------------- launch -----------------------------------------------------
extern "C" void kernel_launch(void* const* d_in, const int* in_sizes, int n_in,
                              void* d_out, int out_size) {
    const float* oh = (const float*)d_in[0];
    // d_in[1] is the scalar `length` (== CTX); rows derived from shape
    const float* Wq = (const float*)d_in[2];
    const float* bq = (const float*)d_in[3];
    const float* Ww = (const float*)d_in[4];
    const float* bw = (const float*)d_in[5];
    float* out = (float*)d_out;

    const int rows = in_sizes[0] / VOCAB;       // 200
    const float inv_len = 1.0f / (float)rows;   // length == CTX here

    w2v_persist<<<GRID, 256>>>(oh, Wq, bq, Ww, bw, out, rows, inv_len);
}